// round 6
// baseline (speedup 1.0000x reference)
#include <cuda_runtime.h>

#define BLOCK_THREADS 256
#define MAX_BLOCKS 4096

__device__ float g_partials[MAX_BLOCKS];
__device__ unsigned int g_done_count = 0;

__device__ __forceinline__ float pick3(float x, float y, float z, int t) {
    float r = (t == 1) ? y : x;
    return (t == 2) ? z : r;
}

__global__ __launch_bounds__(BLOCK_THREADS, 8)
void mtnll_fused_kernel(const float4* __restrict__ in0,   // 4 rows = 3 float4
                        const float4* __restrict__ in1,
                        const float4* __restrict__ in2,
                        const float4* __restrict__ cmap4,
                        const int4* __restrict__ t0q,
                        const int4* __restrict__ t1q,
                        const int4* __restrict__ t2q,
                        float* __restrict__ out,
                        int nq)                            // nq = N/4
{
    float acc = 0.0f;

    const int stride = gridDim.x * blockDim.x;
    for (int i = blockIdx.x * blockDim.x + threadIdx.x; i < nq; i += stride) {
        const int4 a4 = __ldcs(&t0q[i]);
        const int4 b4 = __ldcs(&t1q[i]);
        const int4 c4 = __ldcs(&t2q[i]);
        const float4 w4 = __ldcs(&cmap4[i]);

        const float4 a0 = __ldcs(&in0[3 * i + 0]);
        const float4 a1 = __ldcs(&in0[3 * i + 1]);
        const float4 a2 = __ldcs(&in0[3 * i + 2]);
        const float4 b0 = __ldcs(&in1[3 * i + 0]);
        const float4 b1 = __ldcs(&in1[3 * i + 1]);
        const float4 b2 = __ldcs(&in1[3 * i + 2]);
        const float4 c0 = __ldcs(&in2[3 * i + 0]);
        const float4 c1 = __ldcs(&in2[3 * i + 1]);
        const float4 c2 = __ldcs(&in2[3 * i + 2]);

        // 4 rows per group; layout {r0c0,r0c1,r0c2,r1c0},{r1c1,r1c2,r2c0,r2c1},{r2c2,r3c0,r3c1,r3c2}
        const float p0r0 = pick3(a0.x, a0.y, a0.z, a4.x);
        const float p0r1 = pick3(a0.w, a1.x, a1.y, a4.y);
        const float p0r2 = pick3(a1.z, a1.w, a2.x, a4.z);
        const float p0r3 = pick3(a2.y, a2.z, a2.w, a4.w);

        const float p1r0 = pick3(b0.x, b0.y, b0.z, b4.x);
        const float p1r1 = pick3(b0.w, b1.x, b1.y, b4.y);
        const float p1r2 = pick3(b1.z, b1.w, b2.x, b4.z);
        const float p1r3 = pick3(b2.y, b2.z, b2.w, b4.w);

        const float p2r0 = pick3(c0.x, c0.y, c0.z, c4.x);
        const float p2r1 = pick3(c0.w, c1.x, c1.y, c4.y);
        const float p2r2 = pick3(c1.z, c1.w, c2.x, c4.z);
        const float p2r3 = pick3(c2.y, c2.z, c2.w, c4.w);

        const float s0 = fmaf(0.5f, p1r0, fmaf(0.25f, p2r0, p0r0));
        const float s1 = fmaf(0.5f, p1r1, fmaf(0.25f, p2r1, p0r1));
        const float s2 = fmaf(0.5f, p1r2, fmaf(0.25f, p2r2, p0r2));
        const float s3 = fmaf(0.5f, p1r3, fmaf(0.25f, p2r3, p0r3));

        acc = fmaf(-w4.x, s0, acc);
        acc = fmaf(-w4.y, s1, acc);
        acc = fmaf(-w4.z, s2, acc);
        acc = fmaf(-w4.w, s3, acc);
    }

    // intra-block reduction
    #pragma unroll
    for (int o = 16; o > 0; o >>= 1)
        acc += __shfl_xor_sync(0xffffffffu, acc, o);

    __shared__ float smem[BLOCK_THREADS / 32];
    const int warp = threadIdx.x >> 5;
    const int lane = threadIdx.x & 31;
    if (lane == 0) smem[warp] = acc;
    __syncthreads();

    __shared__ bool s_is_last;
    if (threadIdx.x == 0) {
        float bsum = 0.0f;
        #pragma unroll
        for (int w = 0; w < BLOCK_THREADS / 32; w++) bsum += smem[w];
        g_partials[blockIdx.x] = bsum;
        __threadfence();
        unsigned int prev = atomicAdd(&g_done_count, 1u);
        s_is_last = (prev == gridDim.x - 1);
    }
    __syncthreads();

    if (s_is_last) {
        const int nb = gridDim.x;
        float v = 0.0f;
        for (int j = threadIdx.x; j < nb; j += BLOCK_THREADS)
            v += g_partials[j];
        #pragma unroll
        for (int o = 16; o > 0; o >>= 1)
            v += __shfl_xor_sync(0xffffffffu, v, o);
        if (lane == 0) smem[warp] = v;
        __syncthreads();
        if (threadIdx.x == 0) {
            float total = 0.0f;
            #pragma unroll
            for (int w = 0; w < BLOCK_THREADS / 32; w++) total += smem[w];
            out[0] = total * (1.0f / (float)(4 * nq));
            g_done_count = 0;   // reset for next graph replay
        }
    }
}

extern "C" void kernel_launch(void* const* d_in, const int* in_sizes, int n_in,
                              void* d_out, int out_size) {
    const float4* in0   = (const float4*)d_in[0];
    const float4* in1   = (const float4*)d_in[1];
    const float4* in2   = (const float4*)d_in[2];
    const float4* cmap4 = (const float4*)d_in[3];
    const int4* t0q     = (const int4*)d_in[4];
    const int4* t1q     = (const int4*)d_in[5];
    const int4* t2q     = (const int4*)d_in[6];
    float* out = (float*)d_out;

    const int n = in_sizes[3];   // N; divisible by 4
    const int nq = n / 4;

    // One resident wave: SM count x 8 blocks/SM (regs=32, 256 thr -> occupancy 8).
    // Attribute query is capture-safe (not a stream op); cache it.
    static int s_grid = 0;
    if (s_grid == 0) {
        int sm_count = 0;
        cudaDeviceGetAttribute(&sm_count, cudaDevAttrMultiProcessorCount, 0);
        if (sm_count <= 0) sm_count = 148;
        s_grid = sm_count * 8;
        if (s_grid > MAX_BLOCKS) s_grid = MAX_BLOCKS;
    }

    mtnll_fused_kernel<<<s_grid, BLOCK_THREADS>>>(
        in0, in1, in2, cmap4, t0q, t1q, t2q, out, nq);
}

// round 8
// speedup vs baseline: 1.0674x; 1.0674x over previous
#include <cuda_runtime.h>

#define GRID_BLOCKS 2048
#define BLOCK_THREADS 256

__device__ float g_partials[GRID_BLOCKS];
__device__ unsigned int g_done_count = 0;

__global__ __launch_bounds__(BLOCK_THREADS, 8)
void mtnll_fused_kernel(const float* __restrict__ in0,
                        const float* __restrict__ in1,
                        const float* __restrict__ in2,
                        const float* __restrict__ cmap,
                        const int* __restrict__ t0,
                        const int* __restrict__ t1,
                        const int* __restrict__ t2,
                        float* __restrict__ out,
                        int n)
{
    float acc = 0.0f;

    const int stride = gridDim.x * blockDim.x;   // 524288
    int i = blockIdx.x * blockDim.x + threadIdx.x;

    // 2-way independent unroll: 14 outstanding loads per trip
    for (; i + stride < n; i += 2 * stride) {
        const int j = i + stride;
        // issue all loads before consuming any
        const int   a0 = __ldg(&t0[i]);
        const int   b0 = __ldg(&t1[i]);
        const int   c0 = __ldg(&t2[i]);
        const float w0 = __ldg(&cmap[i]);
        const int   a1 = __ldg(&t0[j]);
        const int   b1 = __ldg(&t1[j]);
        const int   c1 = __ldg(&t2[j]);
        const float w1 = __ldg(&cmap[j]);
        const float p00 = __ldg(&in0[3 * i + a0]);
        const float p01 = __ldg(&in1[3 * i + b0]);
        const float p02 = __ldg(&in2[3 * i + c0]);
        const float p10 = __ldg(&in0[3 * j + a1]);
        const float p11 = __ldg(&in1[3 * j + b1]);
        const float p12 = __ldg(&in2[3 * j + c1]);

        const float s0 = fmaf(0.5f, p01, fmaf(0.25f, p02, p00));
        const float s1 = fmaf(0.5f, p11, fmaf(0.25f, p12, p10));
        acc = fmaf(-w0, s0, acc);
        acc = fmaf(-w1, s1, acc);
    }
    // remainder (at most one trip)
    for (; i < n; i += stride) {
        const int   a = __ldg(&t0[i]);
        const int   b = __ldg(&t1[i]);
        const int   c = __ldg(&t2[i]);
        const float w = __ldg(&cmap[i]);
        const float p0 = __ldg(&in0[3 * i + a]);
        const float p1 = __ldg(&in1[3 * i + b]);
        const float p2 = __ldg(&in2[3 * i + c]);
        const float s = fmaf(0.5f, p1, fmaf(0.25f, p2, p0));
        acc = fmaf(-w, s, acc);
    }

    // intra-block reduction
    #pragma unroll
    for (int o = 16; o > 0; o >>= 1)
        acc += __shfl_xor_sync(0xffffffffu, acc, o);

    __shared__ float smem[BLOCK_THREADS / 32];
    const int warp = threadIdx.x >> 5;
    const int lane = threadIdx.x & 31;
    if (lane == 0) smem[warp] = acc;
    __syncthreads();

    __shared__ bool s_is_last;
    if (threadIdx.x == 0) {
        float bsum = 0.0f;
        #pragma unroll
        for (int w = 0; w < BLOCK_THREADS / 32; w++) bsum += smem[w];
        g_partials[blockIdx.x] = bsum;
        __threadfence();
        unsigned int prev = atomicAdd(&g_done_count, 1u);
        s_is_last = (prev == gridDim.x - 1);
    }
    __syncthreads();

    if (s_is_last) {
        const int nb = gridDim.x;
        float v = 0.0f;
        for (int j = threadIdx.x; j < nb; j += BLOCK_THREADS)
            v += g_partials[j];
        #pragma unroll
        for (int o = 16; o > 0; o >>= 1)
            v += __shfl_xor_sync(0xffffffffu, v, o);
        if (lane == 0) smem[warp] = v;
        __syncthreads();
        if (threadIdx.x == 0) {
            float total = 0.0f;
            #pragma unroll
            for (int w = 0; w < BLOCK_THREADS / 32; w++) total += smem[w];
            out[0] = total * (1.0f / (float)n);
            g_done_count = 0;   // reset for next graph replay
        }
    }
}

extern "C" void kernel_launch(void* const* d_in, const int* in_sizes, int n_in,
                              void* d_out, int out_size) {
    const float* in0  = (const float*)d_in[0];
    const float* in1  = (const float*)d_in[1];
    const float* in2  = (const float*)d_in[2];
    const float* cmap = (const float*)d_in[3];
    const int* t0     = (const int*)d_in[4];
    const int* t1     = (const int*)d_in[5];
    const int* t2     = (const int*)d_in[6];
    float* out = (float*)d_out;

    const int n = in_sizes[3];

    mtnll_fused_kernel<<<GRID_BLOCKS, BLOCK_THREADS>>>(
        in0, in1, in2, cmap, t0, t1, t2, out, n);
}